// round 6
// baseline (speedup 1.0000x reference)
#include <cuda_runtime.h>
#include <cuda_fp16.h>

typedef unsigned int u32;

constexpr int BB   = 4096;
constexpr int SEQN = 49;
constexpr int CC   = 192;
constexpr int HH   = 6;
constexpr int DD   = 32;
constexpr int MROW = BB * SEQN;          // 200704 = 1568 * 128
constexpr float ATT_SCALE = 0.17677669529663687f;  // 32^-0.5

// ---------------- device scratch (static: no allocations allowed) ----------
__device__ __half g_q[(size_t)BB * HH * SEQN * DD];   // [b][h][n][d] fp16
__device__ __half g_k[(size_t)BB * HH * SEQN * DD];
__device__ __half g_v[(size_t)BB * HH * SEQN * DD];
__device__ __half g_o[(size_t)MROW * CC];             // [b*49+n][h*32+d] fp16
__device__ __half g_wqkv_t[576 * 192];                // W^T [n][k]
__device__ __half g_wproj_t[192 * 192];

// ---------------- helpers ---------------------------------------------------
__device__ __forceinline__ u32 pack2(float a, float b) {
    __half2 h = __floats2half2_rn(a, b);
    return *reinterpret_cast<u32*>(&h);
}

__device__ __forceinline__ void mma16816(float* c, const u32* a, const u32* b) {
    asm volatile(
        "mma.sync.aligned.m16n8k16.row.col.f32.f16.f16.f32 "
        "{%0,%1,%2,%3}, {%4,%5,%6,%7}, {%8,%9}, {%0,%1,%2,%3};\n"
        : "+f"(c[0]), "+f"(c[1]), "+f"(c[2]), "+f"(c[3])
        : "r"(a[0]), "r"(a[1]), "r"(a[2]), "r"(a[3]), "r"(b[0]), "r"(b[1]));
}

// ---------------- prep: transpose + fp16-convert weights -------------------
__global__ void prep_kernel(const float* __restrict__ wq, const float* __restrict__ wp) {
    int i = blockIdx.x * blockDim.x + threadIdx.x;
    if (i < 576 * 192) {
        int n = i / 192, k = i - n * 192;
        g_wqkv_t[i] = __float2half_rn(wq[(size_t)k * 576 + n]);
    }
    if (i < 192 * 192) {
        int n = i / 192, k = i - n * 192;
        g_wproj_t[i] = __float2half_rn(wp[(size_t)k * 192 + n]);
    }
}

// ---------------- GEMM 1: qkv = x @ W + b, scatter to q/k/v ----------------
// C[M=200704, N=576], K=192.  Block tile 128x64, BK=16, 256 thr, warp 32x32.
__global__ __launch_bounds__(256) void gemm_qkv_kernel(const float* __restrict__ A,
                                                       const float* __restrict__ bias) {
    __shared__ u32 As[128][8];   // 128 rows x 16 fp16 (k-pairs)
    __shared__ u32 Bs[64][8];    // 64 n-rows x 16 fp16

    const int t = threadIdx.x;
    const int warp = t >> 5, lane = t & 31;
    const int lr = lane >> 2, lw = lane & 3;
    const int wm = (warp >> 1) * 32, wn = (warp & 1) * 32;
    const int m0 = blockIdx.y * 128;
    const int n0 = blockIdx.x * 64;

    float acc[2][4][4] = {};

    for (int kt = 0; kt < 12; ++kt) {
        // A tile: 128x16 fp32 -> fp16
#pragma unroll
        for (int it = 0; it < 2; ++it) {
            int idx = t + it * 256;
            int r = idx >> 2, c4 = idx & 3;
            const float4 f = *(const float4*)(A + (size_t)(m0 + r) * 192 + kt * 16 + c4 * 4);
            As[r][c4 * 2]     = pack2(f.x, f.y);
            As[r][c4 * 2 + 1] = pack2(f.z, f.w);
        }
        // B tile: Wt[n0..n0+63][kt*16..+16]
#pragma unroll
        for (int it = 0; it < 2; ++it) {
            int idx = t + it * 256;
            int n = idx >> 3, wd = idx & 7;
            Bs[n][wd] = *(const u32*)(g_wqkv_t + (size_t)(n0 + n) * 192 + kt * 16 + wd * 2);
        }
        __syncthreads();

        u32 a[2][4], bf[4][2];
#pragma unroll
        for (int mt = 0; mt < 2; ++mt) {
            int row = wm + mt * 16 + lr;
            a[mt][0] = As[row][lw];
            a[mt][1] = As[row + 8][lw];
            a[mt][2] = As[row][lw + 4];
            a[mt][3] = As[row + 8][lw + 4];
        }
#pragma unroll
        for (int nt = 0; nt < 4; ++nt) {
            int nr = wn + nt * 8 + lr;
            bf[nt][0] = Bs[nr][lw];
            bf[nt][1] = Bs[nr][lw + 4];
        }
#pragma unroll
        for (int mt = 0; mt < 2; ++mt)
#pragma unroll
            for (int nt = 0; nt < 4; ++nt)
                mma16816(acc[mt][nt], a[mt], bf[nt]);
        __syncthreads();
    }

    // epilogue: +bias, scatter to q/k/v as [b][h][n][d] fp16
#pragma unroll
    for (int mt = 0; mt < 2; ++mt) {
        int rg0 = m0 + wm + mt * 16 + lr;
        int rg1 = rg0 + 8;
        int b0 = rg0 / 49, p0 = rg0 - b0 * 49;
        int b1 = rg1 / 49, p1 = rg1 - b1 * 49;
#pragma unroll
        for (int nt = 0; nt < 4; ++nt) {
            int col = n0 + wn + nt * 8 + lw * 2;
            int which = col / 192;
            int rem = col - which * 192;
            int hh = rem >> 5, dd = rem & 31;
            __half* dst = (which == 0) ? g_q : (which == 1) ? g_k : g_v;
            float bi0 = bias[col], bi1 = bias[col + 1];
            __half2 v0 = __floats2half2_rn(acc[mt][nt][0] + bi0, acc[mt][nt][1] + bi1);
            __half2 v1 = __floats2half2_rn(acc[mt][nt][2] + bi0, acc[mt][nt][3] + bi1);
            *(__half2*)(dst + ((size_t)(b0 * 6 + hh) * 49 + p0) * 32 + dd) = v0;
            *(__half2*)(dst + ((size_t)(b1 * 6 + hh) * 49 + p1) * 32 + dd) = v1;
        }
    }
}

// ---------------- attention: one (b,h) per block, padded 49 -> 64 ----------
__global__ __launch_bounds__(128) void attn_kernel(const float* __restrict__ mask) {
    __shared__ u32 smem[3072];   // Qs 64x16 | Ks 64x16 | Vt 32x32 (u32 = 2 fp16)
    u32 (*Qs)[16] = (u32(*)[16])smem;
    u32 (*Ks)[16] = (u32(*)[16])(smem + 1024);
    u32 (*Vt)[32] = (u32(*)[32])(smem + 2048);

    const int bh = blockIdx.x;
    const int b = bh / 6, h = bh - b * 6;
    const int w = b & 63;
    const int t = threadIdx.x, warp = t >> 5, lane = t & 31;
    const int lr = lane >> 2, lw = lane & 3;

    // zero pad regions (K/V padding must be exactly 0 -> no NaN/Inf poisoning)
    for (int i = t; i < 3072; i += 128) smem[i] = 0;
    __syncthreads();

    const u32* qg = (const u32*)(g_q + (size_t)bh * SEQN * DD);
    const u32* kg = (const u32*)(g_k + (size_t)bh * SEQN * DD);
    const u32* vg = (const u32*)(g_v + (size_t)bh * SEQN * DD);
    for (int i = t; i < 49 * 16; i += 128) {
        smem[i]        = qg[i];
        smem[1024 + i] = kg[i];
    }
    for (int i = t; i < 49 * 16; i += 128) {   // transpose V -> Vt[d][j]
        u32 u = vg[i];
        int j = i >> 4, wd = i & 15;
        __half2 hv = *(__half2*)&u;
        __half* vth = (__half*)(smem + 2048);
        vth[(2 * wd) * 64 + j]     = __low2half(hv);
        vth[(2 * wd + 1) * 64 + j] = __high2half(hv);
    }
    __syncthreads();

    // S = Q K^T : each warp owns 16 rows x 64 cols
    float s[8][4] = {};
    const int r0 = warp * 16 + lr, r1 = r0 + 8;
    {
        u32 a[2][4];
#pragma unroll
        for (int ks = 0; ks < 2; ++ks) {
            a[ks][0] = Qs[r0][ks * 8 + lw];
            a[ks][1] = Qs[r0 + 8][ks * 8 + lw];
            a[ks][2] = Qs[r0][ks * 8 + lw + 4];
            a[ks][3] = Qs[r0 + 8][ks * 8 + lw + 4];
        }
#pragma unroll
        for (int nt = 0; nt < 8; ++nt) {
            u32 bf0[2], bf1[2];
            bf0[0] = Ks[nt * 8 + lr][lw];     bf0[1] = Ks[nt * 8 + lr][lw + 4];
            bf1[0] = Ks[nt * 8 + lr][8 + lw]; bf1[1] = Ks[nt * 8 + lr][8 + lw + 4];
            mma16816(s[nt], a[0], bf0);
            mma16816(s[nt], a[1], bf1);
        }
    }

    // logits = s*scale + mask, masked softmax (rows r0, r1) in fp32
    const float* m0p = mask + (size_t)w * 2401 + min(r0, 48) * 49;
    const float* m1p = mask + (size_t)w * 2401 + min(r1, 48) * 49;
#pragma unroll
    for (int nt = 0; nt < 8; ++nt) {
        int j0 = nt * 8 + lw * 2, j1 = j0 + 1;
        s[nt][0] = (j0 < 49) ? s[nt][0] * ATT_SCALE + m0p[j0] : -1e30f;
        s[nt][1] = (j1 < 49) ? s[nt][1] * ATT_SCALE + m0p[j1] : -1e30f;
        s[nt][2] = (j0 < 49) ? s[nt][2] * ATT_SCALE + m1p[j0] : -1e30f;
        s[nt][3] = (j1 < 49) ? s[nt][3] * ATT_SCALE + m1p[j1] : -1e30f;
    }
    float mx0 = -1e30f, mx1 = -1e30f;
#pragma unroll
    for (int nt = 0; nt < 8; ++nt) {
        mx0 = fmaxf(mx0, fmaxf(s[nt][0], s[nt][1]));
        mx1 = fmaxf(mx1, fmaxf(s[nt][2], s[nt][3]));
    }
    mx0 = fmaxf(mx0, __shfl_xor_sync(0xffffffffu, mx0, 1));
    mx0 = fmaxf(mx0, __shfl_xor_sync(0xffffffffu, mx0, 2));
    mx1 = fmaxf(mx1, __shfl_xor_sync(0xffffffffu, mx1, 1));
    mx1 = fmaxf(mx1, __shfl_xor_sync(0xffffffffu, mx1, 2));
    float sm0 = 0.f, sm1 = 0.f;
#pragma unroll
    for (int nt = 0; nt < 8; ++nt) {
        s[nt][0] = __expf(s[nt][0] - mx0);
        s[nt][1] = __expf(s[nt][1] - mx0);
        s[nt][2] = __expf(s[nt][2] - mx1);
        s[nt][3] = __expf(s[nt][3] - mx1);
        sm0 += s[nt][0] + s[nt][1];
        sm1 += s[nt][2] + s[nt][3];
    }
    sm0 += __shfl_xor_sync(0xffffffffu, sm0, 1);
    sm0 += __shfl_xor_sync(0xffffffffu, sm0, 2);
    sm1 += __shfl_xor_sync(0xffffffffu, sm1, 1);
    sm1 += __shfl_xor_sync(0xffffffffu, sm1, 2);
    const float inv0 = 1.f / sm0, inv1 = 1.f / sm1;

    // P (fp16 A-fragments), then O = P V
    u32 pa[4][4];
#pragma unroll
    for (int kk = 0; kk < 4; ++kk) {
        pa[kk][0] = pack2(s[2 * kk][0] * inv0, s[2 * kk][1] * inv0);
        pa[kk][1] = pack2(s[2 * kk][2] * inv1, s[2 * kk][3] * inv1);
        pa[kk][2] = pack2(s[2 * kk + 1][0] * inv0, s[2 * kk + 1][1] * inv0);
        pa[kk][3] = pack2(s[2 * kk + 1][2] * inv1, s[2 * kk + 1][3] * inv1);
    }
    float o[4][4] = {};
#pragma unroll
    for (int kk = 0; kk < 4; ++kk)
#pragma unroll
        for (int dt = 0; dt < 4; ++dt) {
            u32 bf[2];
            bf[0] = Vt[dt * 8 + lr][kk * 8 + lw];
            bf[1] = Vt[dt * 8 + lr][kk * 8 + lw + 4];
            mma16816(o[dt], pa[kk], bf);
        }

    // store O as [b*49+n][h*32+d] fp16 for proj GEMM
#pragma unroll
    for (int dt = 0; dt < 4; ++dt) {
        int dd = dt * 8 + lw * 2;
        if (r0 < 49)
            *(__half2*)(g_o + ((size_t)(b * 49 + r0) * 6 + h) * 32 + dd) =
                __floats2half2_rn(o[dt][0], o[dt][1]);
        if (r1 < 49)
            *(__half2*)(g_o + ((size_t)(b * 49 + r1) * 6 + h) * 32 + dd) =
                __floats2half2_rn(o[dt][2], o[dt][3]);
    }
}

// ---------------- GEMM 2: out = O @ proj_w + proj_b (fp32 out) -------------
__global__ __launch_bounds__(256) void gemm_proj_kernel(const float* __restrict__ bias,
                                                        float* __restrict__ out) {
    __shared__ u32 As[128][8];
    __shared__ u32 Bs[64][8];

    const int t = threadIdx.x;
    const int warp = t >> 5, lane = t & 31;
    const int lr = lane >> 2, lw = lane & 3;
    const int wm = (warp >> 1) * 32, wn = (warp & 1) * 32;
    const int m0 = blockIdx.y * 128;
    const int n0 = blockIdx.x * 64;

    float acc[2][4][4] = {};

    for (int kt = 0; kt < 12; ++kt) {
        {   // A tile (fp16 source): 128x16 via one uint4/thread
            int r = t >> 1, c8 = t & 1;
            const uint4 u = *(const uint4*)(g_o + (size_t)(m0 + r) * 192 + kt * 16 + c8 * 8);
            As[r][c8 * 4 + 0] = u.x;
            As[r][c8 * 4 + 1] = u.y;
            As[r][c8 * 4 + 2] = u.z;
            As[r][c8 * 4 + 3] = u.w;
        }
#pragma unroll
        for (int it = 0; it < 2; ++it) {
            int idx = t + it * 256;
            int n = idx >> 3, wd = idx & 7;
            Bs[n][wd] = *(const u32*)(g_wproj_t + (size_t)(n0 + n) * 192 + kt * 16 + wd * 2);
        }
        __syncthreads();

        u32 a[2][4], bf[4][2];
#pragma unroll
        for (int mt = 0; mt < 2; ++mt) {
            int row = wm + mt * 16 + lr;
            a[mt][0] = As[row][lw];
            a[mt][1] = As[row + 8][lw];
            a[mt][2] = As[row][lw + 4];
            a[mt][3] = As[row + 8][lw + 4];
        }
#pragma unroll
        for (int nt = 0; nt < 4; ++nt) {
            int nr = wn + nt * 8 + lr;
            bf[nt][0] = Bs[nr][lw];
            bf[nt][1] = Bs[nr][lw + 4];
        }
#pragma unroll
        for (int mt = 0; mt < 2; ++mt)
#pragma unroll
            for (int nt = 0; nt < 4; ++nt)
                mma16816(acc[mt][nt], a[mt], bf[nt]);
        __syncthreads();
    }

#pragma unroll
    for (int mt = 0; mt < 2; ++mt) {
        int rg0 = m0 + wm + mt * 16 + lr;
        int rg1 = rg0 + 8;
#pragma unroll
        for (int nt = 0; nt < 4; ++nt) {
            int col = n0 + wn + nt * 8 + lw * 2;
            float bi0 = bias[col], bi1 = bias[col + 1];
            float2 v0 = make_float2(acc[mt][nt][0] + bi0, acc[mt][nt][1] + bi1);
            float2 v1 = make_float2(acc[mt][nt][2] + bi0, acc[mt][nt][3] + bi1);
            *(float2*)(out + (size_t)rg0 * 192 + col) = v0;
            *(float2*)(out + (size_t)rg1 * 192 + col) = v1;
        }
    }
}

// ---------------- launch ----------------------------------------------------
extern "C" void kernel_launch(void* const* d_in, const int* in_sizes, int n_in,
                              void* d_out, int out_size) {
    const float* x      = (const float*)d_in[0];
    const float* mask   = (const float*)d_in[1];
    const float* qkv_w  = (const float*)d_in[2];
    const float* qkv_b  = (const float*)d_in[3];
    const float* proj_w = (const float*)d_in[4];
    const float* proj_b = (const float*)d_in[5];
    float* out = (float*)d_out;

    prep_kernel<<<(576 * 192 + 255) / 256, 256>>>(qkv_w, proj_w);
    gemm_qkv_kernel<<<dim3(9, MROW / 128), 256>>>(x, qkv_b);
    attn_kernel<<<BB * HH, 128>>>(mask);
    gemm_proj_kernel<<<dim3(3, MROW / 128), 256>>>(proj_b, out);
}

// round 7
// speedup vs baseline: 1.6164x; 1.6164x over previous
#include <cuda_runtime.h>
#include <cuda_fp16.h>

typedef unsigned int u32;

constexpr int BB   = 4096;
constexpr int SEQN = 49;
constexpr int CC   = 192;
constexpr int HH   = 6;
constexpr int DD   = 32;
constexpr int MROW = BB * SEQN;          // 200704 = 1568 * 128
constexpr float ATT_SCALE = 0.17677669529663687f;  // 32^-0.5

// ---------------- device scratch (static: no allocations allowed) ----------
__device__ __align__(16) __half g_x16[(size_t)MROW * CC];     // x in fp16
__device__ __align__(16) __half g_q[(size_t)BB * HH * SEQN * DD];
__device__ __align__(16) __half g_k[(size_t)BB * HH * SEQN * DD];
__device__ __align__(16) __half g_v[(size_t)BB * HH * SEQN * DD];
__device__ __align__(16) __half g_o[(size_t)MROW * CC];       // [b*49+n][h*32+d]
__device__ __align__(16) __half g_wqkv_t[576 * 192];          // W^T [n][k]
__device__ __align__(16) __half g_wproj_t[192 * 192];

// ---------------- helpers ---------------------------------------------------
__device__ __forceinline__ u32 pack2(float a, float b) {
    __half2 h = __floats2half2_rn(a, b);
    return *reinterpret_cast<u32*>(&h);
}

__device__ __forceinline__ void mma16816(float* c, const u32* a, const u32* b) {
    asm volatile(
        "mma.sync.aligned.m16n8k16.row.col.f32.f16.f16.f32 "
        "{%0,%1,%2,%3}, {%4,%5,%6,%7}, {%8,%9}, {%0,%1,%2,%3};\n"
        : "+f"(c[0]), "+f"(c[1]), "+f"(c[2]), "+f"(c[3])
        : "r"(a[0]), "r"(a[1]), "r"(a[2]), "r"(a[3]), "r"(b[0]), "r"(b[1]));
}

__device__ __forceinline__ void cp16(void* sdst, const void* gsrc) {
    u32 s = (u32)__cvta_generic_to_shared(sdst);
    asm volatile("cp.async.cg.shared.global [%0], [%1], 16;\n" :: "r"(s), "l"(gsrc));
}
__device__ __forceinline__ void cp_commit() {
    asm volatile("cp.async.commit_group;\n");
}

// ---------------- convert x -> fp16 ----------------------------------------
__global__ __launch_bounds__(256) void convert_x_kernel(const float* __restrict__ x) {
    size_t i = (size_t)blockIdx.x * 256 + threadIdx.x;   // one float4 each
    float4 f = ((const float4*)x)[i];
    ((__half2*)g_x16)[2 * i]     = __floats2half2_rn(f.x, f.y);
    ((__half2*)g_x16)[2 * i + 1] = __floats2half2_rn(f.z, f.w);
}

// ---------------- prep: transpose + fp16-convert weights -------------------
__global__ void prep_kernel(const float* __restrict__ wq, const float* __restrict__ wp) {
    int i = blockIdx.x * blockDim.x + threadIdx.x;
    if (i < 576 * 192) {
        int n = i / 192, k = i - n * 192;
        g_wqkv_t[i] = __float2half_rn(wq[(size_t)k * 576 + n]);
    }
    if (i < 192 * 192) {
        int n = i / 192, k = i - n * 192;
        g_wproj_t[i] = __float2half_rn(wp[(size_t)k * 192 + n]);
    }
}

// ============================================================================
// Shared GEMM mainloop: C[128, 64] tile, K=192 in 6 steps of BK=32,
// double-buffered cp.async, padded (stride-20) smem -> conflict-free LDS.
// A: fp16 [M][192], B: fp16 [N][192] (row = output col, K contiguous).
// ============================================================================
struct GemmSmem {
    u32 As[2][128][20];   // 128 rows x 16 data u32 (+4 pad)
    u32 Bs[2][64][20];
};

__device__ __forceinline__ void gemm_mainloop(GemmSmem* sm,
                                              const __half* __restrict__ Ag,
                                              const __half* __restrict__ Bg,
                                              int m0, int n0,
                                              int wm, int wn, int lr, int lw, int t,
                                              float acc[2][4][4]) {
    auto issue = [&](int kt, int s) {
#pragma unroll
        for (int it = 0; it < 2; ++it) {
            int idx = t + it * 256;
            int r = idx >> 2, c = idx & 3;
            cp16(&sm->As[s][r][c * 4], Ag + (size_t)(m0 + r) * 192 + kt * 32 + c * 8);
        }
        {
            int n = t >> 2, c = t & 3;
            cp16(&sm->Bs[s][n][c * 4], Bg + (size_t)(n0 + n) * 192 + kt * 32 + c * 8);
        }
        cp_commit();
    };

    issue(0, 0);
    for (int kt = 0; kt < 6; ++kt) {
        if (kt < 5) {
            issue(kt + 1, (kt + 1) & 1);
            asm volatile("cp.async.wait_group 1;\n");
        } else {
            asm volatile("cp.async.wait_group 0;\n");
        }
        __syncthreads();
        const int s = kt & 1;
#pragma unroll
        for (int ks = 0; ks < 2; ++ks) {
            u32 a[2][4], bf[4][2];
#pragma unroll
            for (int mt = 0; mt < 2; ++mt) {
                int row = wm + mt * 16 + lr;
                a[mt][0] = sm->As[s][row][ks * 8 + lw];
                a[mt][1] = sm->As[s][row + 8][ks * 8 + lw];
                a[mt][2] = sm->As[s][row][ks * 8 + lw + 4];
                a[mt][3] = sm->As[s][row + 8][ks * 8 + lw + 4];
            }
#pragma unroll
            for (int nt = 0; nt < 4; ++nt) {
                int nr = wn + nt * 8 + lr;
                bf[nt][0] = sm->Bs[s][nr][ks * 8 + lw];
                bf[nt][1] = sm->Bs[s][nr][ks * 8 + lw + 4];
            }
#pragma unroll
            for (int mt = 0; mt < 2; ++mt)
#pragma unroll
                for (int nt = 0; nt < 4; ++nt)
                    mma16816(acc[mt][nt], a[mt], bf[nt]);
        }
        __syncthreads();
    }
}

// ---------------- GEMM 1: qkv = x16 @ Wqkv^T + b, scatter to q/k/v ---------
__global__ __launch_bounds__(256) void gemm_qkv_kernel(const float* __restrict__ bias) {
    __shared__ GemmSmem sm;
    const int t = threadIdx.x;
    const int warp = t >> 5, lane = t & 31;
    const int lr = lane >> 2, lw = lane & 3;
    const int wm = (warp >> 1) * 32, wn = (warp & 1) * 32;
    const int m0 = blockIdx.y * 128;
    const int n0 = blockIdx.x * 64;

    float acc[2][4][4] = {};
    gemm_mainloop(&sm, g_x16, g_wqkv_t, m0, n0, wm, wn, lr, lw, t, acc);

#pragma unroll
    for (int mt = 0; mt < 2; ++mt) {
        int rg0 = m0 + wm + mt * 16 + lr;
        int rg1 = rg0 + 8;
        int b0 = rg0 / 49, p0 = rg0 - b0 * 49;
        int b1 = rg1 / 49, p1 = rg1 - b1 * 49;
#pragma unroll
        for (int nt = 0; nt < 4; ++nt) {
            int col = n0 + wn + nt * 8 + lw * 2;
            int which = col / 192;
            int rem = col - which * 192;
            int hh = rem >> 5, dd = rem & 31;
            __half* dst = (which == 0) ? g_q : (which == 1) ? g_k : g_v;
            float bi0 = bias[col], bi1 = bias[col + 1];
            __half2 v0 = __floats2half2_rn(acc[mt][nt][0] + bi0, acc[mt][nt][1] + bi1);
            __half2 v1 = __floats2half2_rn(acc[mt][nt][2] + bi0, acc[mt][nt][3] + bi1);
            *(__half2*)(dst + ((size_t)(b0 * 6 + hh) * 49 + p0) * 32 + dd) = v0;
            *(__half2*)(dst + ((size_t)(b1 * 6 + hh) * 49 + p1) * 32 + dd) = v1;
        }
    }
}

// ---------------- GEMM 2: out = O @ proj_w + proj_b (fp32 out) -------------
__global__ __launch_bounds__(256) void gemm_proj_kernel(const float* __restrict__ bias,
                                                        float* __restrict__ out) {
    __shared__ GemmSmem sm;
    const int t = threadIdx.x;
    const int warp = t >> 5, lane = t & 31;
    const int lr = lane >> 2, lw = lane & 3;
    const int wm = (warp >> 1) * 32, wn = (warp & 1) * 32;
    const int m0 = blockIdx.y * 128;
    const int n0 = blockIdx.x * 64;

    float acc[2][4][4] = {};
    gemm_mainloop(&sm, g_o, g_wproj_t, m0, n0, wm, wn, lr, lw, t, acc);

#pragma unroll
    for (int mt = 0; mt < 2; ++mt) {
        int rg0 = m0 + wm + mt * 16 + lr;
        int rg1 = rg0 + 8;
#pragma unroll
        for (int nt = 0; nt < 4; ++nt) {
            int col = n0 + wn + nt * 8 + lw * 2;
            float bi0 = bias[col], bi1 = bias[col + 1];
            *(float2*)(out + (size_t)rg0 * 192 + col) =
                make_float2(acc[mt][nt][0] + bi0, acc[mt][nt][1] + bi1);
            *(float2*)(out + (size_t)rg1 * 192 + col) =
                make_float2(acc[mt][nt][2] + bi0, acc[mt][nt][3] + bi1);
        }
    }
}

// ---------------- attention: 2 (b,h) per block, 256 threads ----------------
// Per-head smem (u32): Qs 64x20 | Ks 64x20 | Vt 32 u32-rows x 36
constexpr int AQ = 0;
constexpr int AK = 64 * 20;          // 1280
constexpr int AV = 2 * 64 * 20;      // 2560
constexpr int AHEAD = 2560 + 32 * 36; // 3712 u32 per head

__global__ __launch_bounds__(256) void attn_kernel(const float* __restrict__ mask) {
    __shared__ __align__(16) u32 smem_all[2 * AHEAD];

    const int t = threadIdx.x;
    const int sub = t >> 7;              // which head within block
    const int tt = t & 127;
    const int warp = tt >> 5, lane = tt & 31;
    const int lr = lane >> 2, lw = lane & 3;

    const int bh = blockIdx.x * 2 + sub;
    const int b = bh / 6, h = bh - b * 6;
    const int w = b & 63;

    u32* S = smem_all + sub * AHEAD;
    u32 (*Qs)[20] = (u32(*)[20])(S + AQ);
    u32 (*Ks)[20] = (u32(*)[20])(S + AK);
    u32 (*Vt)[36] = (u32(*)[36])(S + AV);

    // zero everything (padding of K/V must be exactly 0)
    for (int i = tt; i < AHEAD; i += 128) S[i] = 0;
    __syncthreads();

    // load q, k (uint4 = 8 halves = 4 data-u32); row r has 4 chunks
    const uint4* qg4 = (const uint4*)(g_q + (size_t)bh * SEQN * DD);
    const uint4* kg4 = (const uint4*)(g_k + (size_t)bh * SEQN * DD);
    for (int i = tt; i < 49 * 4; i += 128) {
        int r = i >> 2, c = i & 3;
        *(uint4*)&Qs[r][c * 4] = qg4[i];
        *(uint4*)&Ks[r][c * 4] = kg4[i];
    }
    // transpose V -> Vt (half view: row stride 72 halves)
    const u32* vg = (const u32*)(g_v + (size_t)bh * SEQN * DD);
    __half* vth = (__half*)(S + AV);
    for (int i = tt; i < 49 * 16; i += 128) {
        u32 u = vg[i];
        int j = i >> 4, wd = i & 15;
        __half2 hv = *(__half2*)&u;
        vth[(2 * wd) * 72 + j]     = __low2half(hv);
        vth[(2 * wd + 1) * 72 + j] = __high2half(hv);
    }
    __syncthreads();

    // S = Q K^T : each warp owns 16 rows x 64 cols
    float s[8][4] = {};
    const int r0 = warp * 16 + lr, r1 = r0 + 8;
    {
        u32 a[2][4];
#pragma unroll
        for (int ks = 0; ks < 2; ++ks) {
            a[ks][0] = Qs[r0][ks * 8 + lw];
            a[ks][1] = Qs[r0 + 8][ks * 8 + lw];
            a[ks][2] = Qs[r0][ks * 8 + lw + 4];
            a[ks][3] = Qs[r0 + 8][ks * 8 + lw + 4];
        }
#pragma unroll
        for (int nt = 0; nt < 8; ++nt) {
            u32 bf0[2], bf1[2];
            bf0[0] = Ks[nt * 8 + lr][lw];     bf0[1] = Ks[nt * 8 + lr][lw + 4];
            bf1[0] = Ks[nt * 8 + lr][8 + lw]; bf1[1] = Ks[nt * 8 + lr][8 + lw + 4];
            mma16816(s[nt], a[0], bf0);
            mma16816(s[nt], a[1], bf1);
        }
    }

    // logits = s*scale + mask, masked softmax (rows r0, r1)
    const float* m0p = mask + (size_t)w * 2401 + min(r0, 48) * 49;
    const float* m1p = mask + (size_t)w * 2401 + min(r1, 48) * 49;
#pragma unroll
    for (int nt = 0; nt < 8; ++nt) {
        int j0 = nt * 8 + lw * 2, j1 = j0 + 1;
        s[nt][0] = (j0 < 49) ? s[nt][0] * ATT_SCALE + m0p[j0] : -1e30f;
        s[nt][1] = (j1 < 49) ? s[nt][1] * ATT_SCALE + m0p[j1] : -1e30f;
        s[nt][2] = (j0 < 49) ? s[nt][2] * ATT_SCALE + m1p[j0] : -1e30f;
        s[nt][3] = (j1 < 49) ? s[nt][3] * ATT_SCALE + m1p[j1] : -1e30f;
    }
    float mx0 = -1e30f, mx1 = -1e30f;
#pragma unroll
    for (int nt = 0; nt < 8; ++nt) {
        mx0 = fmaxf(mx0, fmaxf(s[nt][0], s[nt][1]));
        mx1 = fmaxf(mx1, fmaxf(s[nt][2], s[nt][3]));
    }
    mx0 = fmaxf(mx0, __shfl_xor_sync(0xffffffffu, mx0, 1));
    mx0 = fmaxf(mx0, __shfl_xor_sync(0xffffffffu, mx0, 2));
    mx1 = fmaxf(mx1, __shfl_xor_sync(0xffffffffu, mx1, 1));
    mx1 = fmaxf(mx1, __shfl_xor_sync(0xffffffffu, mx1, 2));
    float sm0 = 0.f, sm1 = 0.f;
#pragma unroll
    for (int nt = 0; nt < 8; ++nt) {
        s[nt][0] = __expf(s[nt][0] - mx0);
        s[nt][1] = __expf(s[nt][1] - mx0);
        s[nt][2] = __expf(s[nt][2] - mx1);
        s[nt][3] = __expf(s[nt][3] - mx1);
        sm0 += s[nt][0] + s[nt][1];
        sm1 += s[nt][2] + s[nt][3];
    }
    sm0 += __shfl_xor_sync(0xffffffffu, sm0, 1);
    sm0 += __shfl_xor_sync(0xffffffffu, sm0, 2);
    sm1 += __shfl_xor_sync(0xffffffffu, sm1, 1);
    sm1 += __shfl_xor_sync(0xffffffffu, sm1, 2);
    const float inv0 = 1.f / sm0, inv1 = 1.f / sm1;

    // P (fp16 A-fragments), then O = P V
    u32 pa[4][4];
#pragma unroll
    for (int kk = 0; kk < 4; ++kk) {
        pa[kk][0] = pack2(s[2 * kk][0] * inv0, s[2 * kk][1] * inv0);
        pa[kk][1] = pack2(s[2 * kk][2] * inv1, s[2 * kk][3] * inv1);
        pa[kk][2] = pack2(s[2 * kk + 1][0] * inv0, s[2 * kk + 1][1] * inv0);
        pa[kk][3] = pack2(s[2 * kk + 1][2] * inv1, s[2 * kk + 1][3] * inv1);
    }
    float o[4][4] = {};
#pragma unroll
    for (int kk = 0; kk < 4; ++kk)
#pragma unroll
        for (int dt = 0; dt < 4; ++dt) {
            u32 bf[2];
            bf[0] = Vt[dt * 8 + lr][kk * 8 + lw];
            bf[1] = Vt[dt * 8 + lr][kk * 8 + lw + 4];
            mma16816(o[dt], pa[kk], bf);
        }

    // store O as [b*49+n][h*32+d] fp16 for proj GEMM
#pragma unroll
    for (int dt = 0; dt < 4; ++dt) {
        int dd = dt * 8 + lw * 2;
        if (r0 < 49)
            *(__half2*)(g_o + ((size_t)(b * 49 + r0) * 6 + h) * 32 + dd) =
                __floats2half2_rn(o[dt][0], o[dt][1]);
        if (r1 < 49)
            *(__half2*)(g_o + ((size_t)(b * 49 + r1) * 6 + h) * 32 + dd) =
                __floats2half2_rn(o[dt][2], o[dt][3]);
    }
}

// ---------------- launch ----------------------------------------------------
extern "C" void kernel_launch(void* const* d_in, const int* in_sizes, int n_in,
                              void* d_out, int out_size) {
    const float* x      = (const float*)d_in[0];
    const float* mask   = (const float*)d_in[1];
    const float* qkv_w  = (const float*)d_in[2];
    const float* qkv_b  = (const float*)d_in[3];
    const float* proj_w = (const float*)d_in[4];
    const float* proj_b = (const float*)d_in[5];
    float* out = (float*)d_out;

    convert_x_kernel<<<(MROW * CC / 4) / 256, 256>>>(x);
    prep_kernel<<<(576 * 192 + 255) / 256, 256>>>(qkv_w, proj_w);
    gemm_qkv_kernel<<<dim3(9, MROW / 128), 256>>>(qkv_b);
    attn_kernel<<<BB * HH / 2, 256>>>(mask);
    gemm_proj_kernel<<<dim3(3, MROW / 128), 256>>>(proj_b, out);
}

// round 10
// speedup vs baseline: 1.9729x; 1.2206x over previous
#include <cuda_runtime.h>
#include <cuda_fp16.h>

typedef unsigned int u32;

constexpr int BB   = 4096;
constexpr int SEQN = 49;
constexpr int CC   = 192;
constexpr int HH   = 6;
constexpr int DD   = 32;
constexpr int MROW = BB * SEQN;          // 200704 = 1568 * 128
constexpr float ATT_SCALE = 0.17677669529663687f;  // 32^-0.5

// ---------------- device scratch (static: no allocations allowed) ----------
__device__ __align__(16) __half g_q[(size_t)BB * HH * SEQN * DD];
__device__ __align__(16) __half g_k[(size_t)BB * HH * SEQN * DD];
__device__ __align__(16) __half g_v[(size_t)BB * HH * SEQN * DD];
__device__ __align__(16) __half g_o[(size_t)MROW * CC];       // [b*49+n][h*32+d]
__device__ __align__(16) __half g_wqkv_t[576 * 192];          // W^T [n][k]
__device__ __align__(16) __half g_wproj_t[192 * 192];

// ---------------- helpers ---------------------------------------------------
__device__ __forceinline__ u32 pack2(float a, float b) {
    __half2 h = __floats2half2_rn(a, b);
    return *reinterpret_cast<u32*>(&h);
}

__device__ __forceinline__ void mma16816(float* c, const u32* a, const u32* b) {
    asm volatile(
        "mma.sync.aligned.m16n8k16.row.col.f32.f16.f16.f32 "
        "{%0,%1,%2,%3}, {%4,%5,%6,%7}, {%8,%9}, {%0,%1,%2,%3};\n"
        : "+f"(c[0]), "+f"(c[1]), "+f"(c[2]), "+f"(c[3])
        : "r"(a[0]), "r"(a[1]), "r"(a[2]), "r"(a[3]), "r"(b[0]), "r"(b[1]));
}

__device__ __forceinline__ void ldsm4(u32* r, const void* p) {
    u32 a = (u32)__cvta_generic_to_shared(p);
    asm volatile("ldmatrix.sync.aligned.m8n8.x4.shared.b16 {%0,%1,%2,%3}, [%4];"
        : "=r"(r[0]), "=r"(r[1]), "=r"(r[2]), "=r"(r[3]) : "r"(a));
}
__device__ __forceinline__ void ldsm4t(u32* r, const void* p) {
    u32 a = (u32)__cvta_generic_to_shared(p);
    asm volatile("ldmatrix.sync.aligned.m8n8.x4.trans.shared.b16 {%0,%1,%2,%3}, [%4];"
        : "=r"(r[0]), "=r"(r[1]), "=r"(r[2]), "=r"(r[3]) : "r"(a));
}

__device__ __forceinline__ void cp16(void* sdst, const void* gsrc) {
    u32 s = (u32)__cvta_generic_to_shared(sdst);
    asm volatile("cp.async.cg.shared.global [%0], [%1], 16;\n" :: "r"(s), "l"(gsrc));
}
__device__ __forceinline__ void cp_commit() { asm volatile("cp.async.commit_group;\n"); }

// ---------------- prep: transpose + fp16-convert weights -------------------
__global__ void prep_kernel(const float* __restrict__ wq, const float* __restrict__ wp) {
    int i = blockIdx.x * blockDim.x + threadIdx.x;
    if (i < 576 * 192) {
        int n = i / 192, k = i - n * 192;
        g_wqkv_t[i] = __float2half_rn(wq[(size_t)k * 576 + n]);
    }
    if (i < 192 * 192) {
        int n = i / 192, k = i - n * 192;
        g_wproj_t[i] = __float2half_rn(wp[(size_t)k * 192 + n]);
    }
}

// ============================================================================
// Persistent-A GEMM: block computes C[128, NT*64], K=192.
// A (128x192 fp16) staged once in smem, all A-fragments hoisted to registers.
// B tiles (64x192) double-buffered via cp.async; ONE __syncthreads per n-tile.
// ============================================================================
struct GSmem {
    __half A[128][200];        // stride 200 halves (400B): conflict-free ldmatrix
    __half B[2][64][200];
};
constexpr unsigned GSMEM_BYTES = sizeof(GSmem);   // 102400

#define GEMM_ISSUE_B(Bg, nt, s)                                                \
    do {                                                                       \
        _Pragma("unroll")                                                      \
        for (int i_ = 0; i_ < 6; ++i_) {                                       \
            int idx_ = t + i_ * 256;                                           \
            int r_ = idx_ / 24, c_ = idx_ - r_ * 24;                           \
            cp16(&sm.B[s][r_][c_ * 8],                                         \
                 (Bg) + (size_t)((nt) * 64 + r_) * 192 + c_ * 8);              \
        }                                                                      \
        cp_commit();                                                           \
    } while (0)

#define GEMM_COMPUTE(s, acc)                                                   \
    do {                                                                       \
        _Pragma("unroll")                                                      \
        for (int ks = 0; ks < 12; ++ks) {                                      \
            u32 bfr[2][4];                                                     \
            ldsm4(bfr[0], &sm.B[s][wn + brow][ks * 16 + bcol]);                \
            ldsm4(bfr[1], &sm.B[s][wn + 16 + brow][ks * 16 + bcol]);           \
            _Pragma("unroll")                                                  \
            for (int mt = 0; mt < 2; ++mt) {                                   \
                mma16816(acc[mt][0], afr[ks][mt], &bfr[0][0]);                 \
                mma16816(acc[mt][1], afr[ks][mt], &bfr[0][2]);                 \
                mma16816(acc[mt][2], afr[ks][mt], &bfr[1][0]);                 \
                mma16816(acc[mt][3], afr[ks][mt], &bfr[1][2]);                 \
            }                                                                  \
        }                                                                      \
    } while (0)

// ---------------- GEMM 1: qkv = x @ Wqkv^T + b, scatter to q/k/v -----------
__global__ __launch_bounds__(256, 1) void gemm_qkv_kernel(const float* __restrict__ x,
                                                          const float* __restrict__ bias) {
    extern __shared__ __align__(16) char dsm[];
    GSmem& sm = *(GSmem*)dsm;
    const int t = threadIdx.x;
    const int warp = t >> 5, lane = t & 31;
    const int lr = lane >> 2, lw = lane & 3;
    const int wm = (warp >> 1) * 32, wn = (warp & 1) * 32;
    const int m0 = blockIdx.x * 128;
    const int lrow = lane & 15, lcol = (lane >> 4) << 3;
    const int brow = (lane & 7) + ((lane & 16) >> 1);
    const int bcol = (lane & 8);

    GEMM_ISSUE_B(g_wqkv_t, 0, 0);

    // A: fp32 x -> fp16 smem (24 float4 per thread)
    const float4* X4 = (const float4*)x + (size_t)m0 * 48;
#pragma unroll
    for (int i = 0; i < 24; ++i) {
        int idx = t + i * 256;
        int r = idx / 48, c = idx - r * 48;
        float4 f = X4[(size_t)r * 48 + c];
        __half2* dst = (__half2*)&sm.A[r][c * 4];
        dst[0] = __floats2half2_rn(f.x, f.y);
        dst[1] = __floats2half2_rn(f.z, f.w);
    }
    __syncthreads();

    // hoist all A fragments into registers
    u32 afr[12][2][4];
#pragma unroll
    for (int ks = 0; ks < 12; ++ks)
#pragma unroll
        for (int mt = 0; mt < 2; ++mt)
            ldsm4(afr[ks][mt], &sm.A[wm + mt * 16 + lrow][ks * 16 + lcol]);

    for (int nt = 0; nt < 9; ++nt) {
        asm volatile("cp.async.wait_group 0;\n" ::: "memory");
        __syncthreads();
        if (nt + 1 < 9) GEMM_ISSUE_B(g_wqkv_t, nt + 1, (nt + 1) & 1);
        const int s = nt & 1;
        float acc[2][4][4] = {};
        GEMM_COMPUTE(s, acc);

        // epilogue: +bias, scatter to q/k/v as [b][h][n][d]
        const int colbase = nt * 64 + wn;
#pragma unroll
        for (int mt = 0; mt < 2; ++mt) {
            int rg0 = m0 + wm + mt * 16 + lr;
            int rg1 = rg0 + 8;
            int b0 = rg0 / 49, p0 = rg0 - b0 * 49;
            int b1 = rg1 / 49, p1 = rg1 - b1 * 49;
#pragma unroll
            for (int j = 0; j < 4; ++j) {
                int col = colbase + j * 8 + lw * 2;
                int which = col / 192;
                int rem = col - which * 192;
                int hh = rem >> 5, dd = rem & 31;
                __half* dst = (which == 0) ? g_q : (which == 1) ? g_k : g_v;
                float bi0 = bias[col], bi1 = bias[col + 1];
                __half2 v0 = __floats2half2_rn(acc[mt][j][0] + bi0, acc[mt][j][1] + bi1);
                __half2 v1 = __floats2half2_rn(acc[mt][j][2] + bi0, acc[mt][j][3] + bi1);
                *(__half2*)(dst + ((size_t)(b0 * 6 + hh) * 49 + p0) * 32 + dd) = v0;
                *(__half2*)(dst + ((size_t)(b1 * 6 + hh) * 49 + p1) * 32 + dd) = v1;
            }
        }
    }
}

// ---------------- GEMM 2: out = O @ proj_w + proj_b (fp32 out) -------------
__global__ __launch_bounds__(256, 1) void gemm_proj_kernel(const float* __restrict__ bias,
                                                           float* __restrict__ out) {
    extern __shared__ __align__(16) char dsm[];
    GSmem& sm = *(GSmem*)dsm;
    const int t = threadIdx.x;
    const int warp = t >> 5, lane = t & 31;
    const int lr = lane >> 2, lw = lane & 3;
    const int wm = (warp >> 1) * 32, wn = (warp & 1) * 32;
    const int m0 = blockIdx.x * 128;
    const int lrow = lane & 15, lcol = (lane >> 4) << 3;
    const int brow = (lane & 7) + ((lane & 16) >> 1);
    const int bcol = (lane & 8);

    // A (fp16) via cp.async — its own group
#pragma unroll
    for (int i = 0; i < 12; ++i) {
        int idx = t + i * 256;
        int r = idx / 24, c = idx - r * 24;
        cp16(&sm.A[r][c * 8], g_o + (size_t)(m0 + r) * 192 + c * 8);
    }
    cp_commit();
    GEMM_ISSUE_B(g_wproj_t, 0, 0);

    asm volatile("cp.async.wait_group 1;\n" ::: "memory");   // A done
    __syncthreads();

    u32 afr[12][2][4];
#pragma unroll
    for (int ks = 0; ks < 12; ++ks)
#pragma unroll
        for (int mt = 0; mt < 2; ++mt)
            ldsm4(afr[ks][mt], &sm.A[wm + mt * 16 + lrow][ks * 16 + lcol]);

    for (int nt = 0; nt < 3; ++nt) {
        asm volatile("cp.async.wait_group 0;\n" ::: "memory");
        __syncthreads();
        if (nt + 1 < 3) GEMM_ISSUE_B(g_wproj_t, nt + 1, (nt + 1) & 1);
        const int s = nt & 1;
        float acc[2][4][4] = {};
        GEMM_COMPUTE(s, acc);

        const int colbase = nt * 64 + wn;
#pragma unroll
        for (int mt = 0; mt < 2; ++mt) {
            int rg0 = m0 + wm + mt * 16 + lr;
            int rg1 = rg0 + 8;
#pragma unroll
            for (int j = 0; j < 4; ++j) {
                int col = colbase + j * 8 + lw * 2;
                float bi0 = bias[col], bi1 = bias[col + 1];
                *(float2*)(out + (size_t)rg0 * 192 + col) =
                    make_float2(acc[mt][j][0] + bi0, acc[mt][j][1] + bi1);
                *(float2*)(out + (size_t)rg1 * 192 + col) =
                    make_float2(acc[mt][j][2] + bi0, acc[mt][j][3] + bi1);
            }
        }
    }
}

// ---------------- attention: 2 (b,h) per block, ldmatrix everywhere --------
__global__ __launch_bounds__(256) void attn_kernel(const float* __restrict__ mask) {
    __shared__ __align__(16) __half sQ[2][64][40];
    __shared__ __align__(16) __half sK[2][64][40];
    __shared__ __align__(16) __half sV[2][64][40];

    const int t = threadIdx.x;
    const int sub = t >> 7;
    const int tt = t & 127;
    const int warp = tt >> 5, lane = tt & 31;
    const int lr = lane >> 2, lw = lane & 3;
    const int lrow = lane & 15, lcol = (lane >> 4) << 3;
    const int brow = (lane & 7) + ((lane & 16) >> 1);
    const int bcol = (lane & 8);

    const int bh = blockIdx.x * 2 + sub;
    const int b = bh / 6, h = bh - b * 6;
    const int w = b & 63;

    // async q/k/v loads: 49 rows x 32 halves = 64 bytes = FOUR 16B chunks/row
    {
        const char* qg = (const char*)(g_q + (size_t)bh * 1568);
        const char* kg = (const char*)(g_k + (size_t)bh * 1568);
        const char* vg = (const char*)(g_v + (size_t)bh * 1568);
        for (int i = tt; i < 196; i += 128) {
            int r = i >> 2, c = i & 3;
            cp16(&sQ[sub][r][c * 8], qg + r * 64 + c * 16);
            cp16(&sK[sub][r][c * 8], kg + r * 64 + c * 16);
            cp16(&sV[sub][r][c * 8], vg + r * 64 + c * 16);
        }
        cp_commit();
        // zero V pad rows 49..63 (only V pad matters: P[j>=49] == 0, avoid NaN)
        for (int i = tt; i < 15 * 20; i += 128) {
            int r = 49 + i / 20, c = i - (i / 20) * 20;
            ((u32*)&sV[sub][r][0])[c] = 0u;
        }
        asm volatile("cp.async.wait_all;\n" ::: "memory");
    }
    __syncthreads();

    // Q fragments (16 rows per warp, k = 0..31)
    u32 qa[2][4];
    ldsm4(qa[0], &sQ[sub][warp * 16 + lrow][lcol]);
    ldsm4(qa[1], &sQ[sub][warp * 16 + lrow][16 + lcol]);

    // S = Q K^T : warp owns 16 rows x 64 cols
    float s[8][4] = {};
#pragma unroll
    for (int g = 0; g < 4; ++g) {
        u32 kb[2][4];
        ldsm4(kb[0], &sK[sub][g * 16 + brow][bcol]);        // k 0..15
        ldsm4(kb[1], &sK[sub][g * 16 + brow][16 + bcol]);   // k 16..31
        mma16816(s[2 * g],     qa[0], &kb[0][0]);
        mma16816(s[2 * g],     qa[1], &kb[1][0]);
        mma16816(s[2 * g + 1], qa[0], &kb[0][2]);
        mma16816(s[2 * g + 1], qa[1], &kb[1][2]);
    }

    // logits = s*scale + mask, masked softmax (rows r0, r1)
    const int r0 = warp * 16 + lr, r1 = r0 + 8;
    const float* m0p = mask + (size_t)w * 2401 + min(r0, 48) * 49;
    const float* m1p = mask + (size_t)w * 2401 + min(r1, 48) * 49;
#pragma unroll
    for (int nt = 0; nt < 8; ++nt) {
        int j0 = nt * 8 + lw * 2, j1 = j0 + 1;
        s[nt][0] = (j0 < 49) ? s[nt][0] * ATT_SCALE + m0p[j0] : -1e30f;
        s[nt][1] = (j1 < 49) ? s[nt][1] * ATT_SCALE + m0p[j1] : -1e30f;
        s[nt][2] = (j0 < 49) ? s[nt][2] * ATT_SCALE + m1p[j0] : -1e30f;
        s[nt][3] = (j1 < 49) ? s[nt][3] * ATT_SCALE + m1p[j1] : -1e30f;
    }
    float mx0 = -1e30f, mx1 = -1e30f;
#pragma unroll
    for (int nt = 0; nt < 8; ++nt) {
        mx0 = fmaxf(mx0, fmaxf(s[nt][0], s[nt][1]));
        mx1 = fmaxf(mx1, fmaxf(s[nt][2], s[nt][3]));
    }
    mx0 = fmaxf(mx0, __shfl_xor_sync(0xffffffffu, mx0, 1));
    mx0 = fmaxf(mx0, __shfl_xor_sync(0xffffffffu, mx0, 2));
    mx1 = fmaxf(mx1, __shfl_xor_sync(0xffffffffu, mx1, 1));
    mx1 = fmaxf(mx1, __shfl_xor_sync(0xffffffffu, mx1, 2));
    float sm0 = 0.f, sm1 = 0.f;
#pragma unroll
    for (int nt = 0; nt < 8; ++nt) {
        s[nt][0] = __expf(s[nt][0] - mx0);
        s[nt][1] = __expf(s[nt][1] - mx0);
        s[nt][2] = __expf(s[nt][2] - mx1);
        s[nt][3] = __expf(s[nt][3] - mx1);
        sm0 += s[nt][0] + s[nt][1];
        sm1 += s[nt][2] + s[nt][3];
    }
    sm0 += __shfl_xor_sync(0xffffffffu, sm0, 1);
    sm0 += __shfl_xor_sync(0xffffffffu, sm0, 2);
    sm1 += __shfl_xor_sync(0xffffffffu, sm1, 1);
    sm1 += __shfl_xor_sync(0xffffffffu, sm1, 2);
    const float inv0 = 1.f / sm0, inv1 = 1.f / sm1;

    // P (fp16 A-fragments), then O = P V  (V B-frags via ldmatrix.trans)
    u32 pa[4][4];
#pragma unroll
    for (int kk = 0; kk < 4; ++kk) {
        pa[kk][0] = pack2(s[2 * kk][0] * inv0, s[2 * kk][1] * inv0);
        pa[kk][1] = pack2(s[2 * kk][2] * inv1, s[2 * kk][3] * inv1);
        pa[kk][2] = pack2(s[2 * kk + 1][0] * inv0, s[2 * kk + 1][1] * inv0);
        pa[kk][3] = pack2(s[2 * kk + 1][2] * inv1, s[2 * kk + 1][3] * inv1);
    }
    float o[4][4] = {};
#pragma unroll
    for (int kk = 0; kk < 4; ++kk) {
        u32 vb[2][4];
        ldsm4t(vb[0], &sV[sub][kk * 16 + lrow][lcol]);        // d 0..15
        ldsm4t(vb[1], &sV[sub][kk * 16 + lrow][16 + lcol]);   // d 16..31
        mma16816(o[0], pa[kk], &vb[0][0]);
        mma16816(o[1], pa[kk], &vb[0][2]);
        mma16816(o[2], pa[kk], &vb[1][0]);
        mma16816(o[3], pa[kk], &vb[1][2]);
    }

    // store O as [b*49+n][h*32+d] fp16 for proj GEMM
#pragma unroll
    for (int dt = 0; dt < 4; ++dt) {
        int dd = dt * 8 + lw * 2;
        if (r0 < 49)
            *(__half2*)(g_o + ((size_t)(b * 49 + r0) * 6 + h) * 32 + dd) =
                __floats2half2_rn(o[dt][0], o[dt][1]);
        if (r1 < 49)
            *(__half2*)(g_o + ((size_t)(b * 49 + r1) * 6 + h) * 32 + dd) =
                __floats2half2_rn(o[dt][2], o[dt][3]);
    }
}

// ---------------- launch ----------------------------------------------------
extern "C" void kernel_launch(void* const* d_in, const int* in_sizes, int n_in,
                              void* d_out, int out_size) {
    const float* x      = (const float*)d_in[0];
    const float* mask   = (const float*)d_in[1];
    const float* qkv_w  = (const float*)d_in[2];
    const float* qkv_b  = (const float*)d_in[3];
    const float* proj_w = (const float*)d_in[4];
    const float* proj_b = (const float*)d_in[5];
    float* out = (float*)d_out;

    cudaFuncSetAttribute(gemm_qkv_kernel,
                         cudaFuncAttributeMaxDynamicSharedMemorySize, GSMEM_BYTES);
    cudaFuncSetAttribute(gemm_proj_kernel,
                         cudaFuncAttributeMaxDynamicSharedMemorySize, GSMEM_BYTES);

    prep_kernel<<<(576 * 192 + 255) / 256, 256>>>(qkv_w, proj_w);
    gemm_qkv_kernel<<<MROW / 128, 256, GSMEM_BYTES>>>(x, qkv_b);
    attn_kernel<<<BB * HH / 2, 256>>>(mask);
    gemm_proj_kernel<<<MROW / 128, 256, GSMEM_BYTES>>>(proj_b, out);
}

// round 11
// speedup vs baseline: 1.9895x; 1.0084x over previous
#include <cuda_runtime.h>
#include <cuda_fp16.h>

typedef unsigned int u32;

constexpr int BB   = 4096;
constexpr int SEQN = 49;
constexpr int CC   = 192;
constexpr int HH   = 6;
constexpr int DD   = 32;
constexpr int MROW = BB * SEQN;          // 200704 = 1568 * 128
constexpr float ATT_SCALE = 0.17677669529663687f;  // 32^-0.5

// ---------------- device scratch (static: no allocations allowed) ----------
__device__ __align__(16) __half g_q[(size_t)BB * HH * SEQN * DD];
__device__ __align__(16) __half g_k[(size_t)BB * HH * SEQN * DD];
__device__ __align__(16) __half g_v[(size_t)BB * HH * SEQN * DD];
__device__ __align__(16) __half g_o[(size_t)MROW * CC];       // [b*49+n][h*32+d]
__device__ __align__(16) __half g_wqkv_t[576 * 192];          // W^T [n][k]
__device__ __align__(16) __half g_wproj_t[192 * 192];

// ---------------- helpers ---------------------------------------------------
__device__ __forceinline__ u32 pack2(float a, float b) {
    __half2 h = __floats2half2_rn(a, b);
    return *reinterpret_cast<u32*>(&h);
}

__device__ __forceinline__ void mma16816(float* c, const u32* a, const u32* b) {
    asm volatile(
        "mma.sync.aligned.m16n8k16.row.col.f32.f16.f16.f32 "
        "{%0,%1,%2,%3}, {%4,%5,%6,%7}, {%8,%9}, {%0,%1,%2,%3};\n"
        : "+f"(c[0]), "+f"(c[1]), "+f"(c[2]), "+f"(c[3])
        : "r"(a[0]), "r"(a[1]), "r"(a[2]), "r"(a[3]), "r"(b[0]), "r"(b[1]));
}

__device__ __forceinline__ void ldsm4(u32* r, const void* p) {
    u32 a = (u32)__cvta_generic_to_shared(p);
    asm volatile("ldmatrix.sync.aligned.m8n8.x4.shared.b16 {%0,%1,%2,%3}, [%4];"
        : "=r"(r[0]), "=r"(r[1]), "=r"(r[2]), "=r"(r[3]) : "r"(a));
}
__device__ __forceinline__ void ldsm4t(u32* r, const void* p) {
    u32 a = (u32)__cvta_generic_to_shared(p);
    asm volatile("ldmatrix.sync.aligned.m8n8.x4.trans.shared.b16 {%0,%1,%2,%3}, [%4];"
        : "=r"(r[0]), "=r"(r[1]), "=r"(r[2]), "=r"(r[3]) : "r"(a));
}

__device__ __forceinline__ void cp16(void* sdst, const void* gsrc) {
    u32 s = (u32)__cvta_generic_to_shared(sdst);
    asm volatile("cp.async.cg.shared.global [%0], [%1], 16;\n" :: "r"(s), "l"(gsrc));
}
__device__ __forceinline__ void cp_commit() { asm volatile("cp.async.commit_group;\n"); }

// ---------------- prep: transpose + fp16-convert weights -------------------
__global__ void prep_kernel(const float* __restrict__ wq, const float* __restrict__ wp) {
    int i = blockIdx.x * blockDim.x + threadIdx.x;
    if (i < 576 * 192) {
        int n = i / 192, k = i - n * 192;
        g_wqkv_t[i] = __float2half_rn(wq[(size_t)k * 576 + n]);
    }
    if (i < 192 * 192) {
        int n = i / 192, k = i - n * 192;
        g_wproj_t[i] = __float2half_rn(wp[(size_t)k * 192 + n]);
    }
}

// ============================================================================
// Persistent-A GEMM: block computes C[128, NT*64], K=192.
// A (128x192 fp16) staged once in smem, all A-fragments hoisted to registers.
// B tiles (64x192) double-buffered via cp.async; ONE __syncthreads per n-tile.
// ============================================================================
struct GSmem {
    __half A[128][200];        // stride 200 halves (400B): conflict-free ldmatrix
    __half B[2][64][200];
};
constexpr unsigned GSMEM_BYTES = sizeof(GSmem);   // 102400

#define GEMM_ISSUE_B(Bg, nt, s)                                                \
    do {                                                                       \
        _Pragma("unroll")                                                      \
        for (int i_ = 0; i_ < 6; ++i_) {                                       \
            int idx_ = t + i_ * 256;                                           \
            int r_ = idx_ / 24, c_ = idx_ - r_ * 24;                           \
            cp16(&sm.B[s][r_][c_ * 8],                                         \
                 (Bg) + (size_t)((nt) * 64 + r_) * 192 + c_ * 8);              \
        }                                                                      \
        cp_commit();                                                           \
    } while (0)

#define GEMM_COMPUTE(s, acc)                                                   \
    do {                                                                       \
        _Pragma("unroll")                                                      \
        for (int ks = 0; ks < 12; ++ks) {                                      \
            u32 bfr[2][4];                                                     \
            ldsm4(bfr[0], &sm.B[s][wn + brow][ks * 16 + bcol]);                \
            ldsm4(bfr[1], &sm.B[s][wn + 16 + brow][ks * 16 + bcol]);           \
            _Pragma("unroll")                                                  \
            for (int mt = 0; mt < 2; ++mt) {                                   \
                mma16816(acc[mt][0], afr[ks][mt], &bfr[0][0]);                 \
                mma16816(acc[mt][1], afr[ks][mt], &bfr[0][2]);                 \
                mma16816(acc[mt][2], afr[ks][mt], &bfr[1][0]);                 \
                mma16816(acc[mt][3], afr[ks][mt], &bfr[1][2]);                 \
            }                                                                  \
        }                                                                      \
    } while (0)

// ---------------- GEMM 1: qkv = x @ Wqkv^T + b, scatter to q/k/v -----------
__global__ __launch_bounds__(256, 1) void gemm_qkv_kernel(const float* __restrict__ x,
                                                          const float* __restrict__ bias) {
    extern __shared__ __align__(16) char dsm[];
    GSmem& sm = *(GSmem*)dsm;
    const int t = threadIdx.x;
    const int warp = t >> 5, lane = t & 31;
    const int lr = lane >> 2, lw = lane & 3;
    const int wm = (warp >> 1) * 32, wn = (warp & 1) * 32;
    const int m0 = blockIdx.x * 128;
    const int lrow = lane & 15, lcol = (lane >> 4) << 3;
    const int brow = (lane & 7) + ((lane & 16) >> 1);
    const int bcol = (lane & 8);

    GEMM_ISSUE_B(g_wqkv_t, 0, 0);

    // A: fp32 x -> fp16 smem (24 float4 per thread)
    const float4* X4 = (const float4*)x + (size_t)m0 * 48;
#pragma unroll
    for (int i = 0; i < 24; ++i) {
        int idx = t + i * 256;
        int r = idx / 48, c = idx - r * 48;
        float4 f = X4[(size_t)r * 48 + c];
        __half2* dst = (__half2*)&sm.A[r][c * 4];
        dst[0] = __floats2half2_rn(f.x, f.y);
        dst[1] = __floats2half2_rn(f.z, f.w);
    }
    __syncthreads();

    // hoist all A fragments into registers
    u32 afr[12][2][4];
#pragma unroll
    for (int ks = 0; ks < 12; ++ks)
#pragma unroll
        for (int mt = 0; mt < 2; ++mt)
            ldsm4(afr[ks][mt], &sm.A[wm + mt * 16 + lrow][ks * 16 + lcol]);

    for (int nt = 0; nt < 9; ++nt) {
        asm volatile("cp.async.wait_group 0;\n" ::: "memory");
        __syncthreads();
        if (nt + 1 < 9) GEMM_ISSUE_B(g_wqkv_t, nt + 1, (nt + 1) & 1);
        const int s = nt & 1;
        float acc[2][4][4] = {};
        GEMM_COMPUTE(s, acc);

        // epilogue: +bias, scatter to q/k/v as [b][h][n][d]
        const int colbase = nt * 64 + wn;
#pragma unroll
        for (int mt = 0; mt < 2; ++mt) {
            int rg0 = m0 + wm + mt * 16 + lr;
            int rg1 = rg0 + 8;
            int b0 = rg0 / 49, p0 = rg0 - b0 * 49;
            int b1 = rg1 / 49, p1 = rg1 - b1 * 49;
#pragma unroll
            for (int j = 0; j < 4; ++j) {
                int col = colbase + j * 8 + lw * 2;
                int which = col / 192;
                int rem = col - which * 192;
                int hh = rem >> 5, dd = rem & 31;
                __half* dst = (which == 0) ? g_q : (which == 1) ? g_k : g_v;
                float bi0 = bias[col], bi1 = bias[col + 1];
                __half2 v0 = __floats2half2_rn(acc[mt][j][0] + bi0, acc[mt][j][1] + bi1);
                __half2 v1 = __floats2half2_rn(acc[mt][j][2] + bi0, acc[mt][j][3] + bi1);
                *(__half2*)(dst + ((size_t)(b0 * 6 + hh) * 49 + p0) * 32 + dd) = v0;
                *(__half2*)(dst + ((size_t)(b1 * 6 + hh) * 49 + p1) * 32 + dd) = v1;
            }
        }
    }
}

// ---------------- GEMM 2: out = O @ proj_w + proj_b (fp32 out) -------------
__global__ __launch_bounds__(256, 1) void gemm_proj_kernel(const float* __restrict__ bias,
                                                           float* __restrict__ out) {
    extern __shared__ __align__(16) char dsm[];
    GSmem& sm = *(GSmem*)dsm;
    const int t = threadIdx.x;
    const int warp = t >> 5, lane = t & 31;
    const int lr = lane >> 2, lw = lane & 3;
    const int wm = (warp >> 1) * 32, wn = (warp & 1) * 32;
    const int m0 = blockIdx.x * 128;
    const int lrow = lane & 15, lcol = (lane >> 4) << 3;
    const int brow = (lane & 7) + ((lane & 16) >> 1);
    const int bcol = (lane & 8);

    // A (fp16) via cp.async — its own group
#pragma unroll
    for (int i = 0; i < 12; ++i) {
        int idx = t + i * 256;
        int r = idx / 24, c = idx - r * 24;
        cp16(&sm.A[r][c * 8], g_o + (size_t)(m0 + r) * 192 + c * 8);
    }
    cp_commit();
    GEMM_ISSUE_B(g_wproj_t, 0, 0);

    asm volatile("cp.async.wait_group 1;\n" ::: "memory");   // A done
    __syncthreads();

    u32 afr[12][2][4];
#pragma unroll
    for (int ks = 0; ks < 12; ++ks)
#pragma unroll
        for (int mt = 0; mt < 2; ++mt)
            ldsm4(afr[ks][mt], &sm.A[wm + mt * 16 + lrow][ks * 16 + lcol]);

    for (int nt = 0; nt < 3; ++nt) {
        asm volatile("cp.async.wait_group 0;\n" ::: "memory");
        __syncthreads();
        if (nt + 1 < 3) GEMM_ISSUE_B(g_wproj_t, nt + 1, (nt + 1) & 1);
        const int s = nt & 1;
        float acc[2][4][4] = {};
        GEMM_COMPUTE(s, acc);

        const int colbase = nt * 64 + wn;
#pragma unroll
        for (int mt = 0; mt < 2; ++mt) {
            int rg0 = m0 + wm + mt * 16 + lr;
            int rg1 = rg0 + 8;
#pragma unroll
            for (int j = 0; j < 4; ++j) {
                int col = colbase + j * 8 + lw * 2;
                float bi0 = bias[col], bi1 = bias[col + 1];
                *(float2*)(out + (size_t)rg0 * 192 + col) =
                    make_float2(acc[mt][j][0] + bi0, acc[mt][j][1] + bi1);
                *(float2*)(out + (size_t)rg1 * 192 + col) =
                    make_float2(acc[mt][j][2] + bi0, acc[mt][j][3] + bi1);
            }
        }
    }
}

// ---------------- attention: 2 (b,h) per block, ldmatrix everywhere --------
__global__ __launch_bounds__(256) void attn_kernel(const float* __restrict__ mask) {
    __shared__ __align__(16) __half sQ[2][64][40];
    __shared__ __align__(16) __half sK[2][64][40];
    __shared__ __align__(16) __half sV[2][64][40];

    const int t = threadIdx.x;
    const int sub = t >> 7;
    const int tt = t & 127;
    const int warp = tt >> 5, lane = tt & 31;
    const int lr = lane >> 2, lw = lane & 3;
    const int lrow = lane & 15, lcol = (lane >> 4) << 3;
    const int brow = (lane & 7) + ((lane & 16) >> 1);
    const int bcol = (lane & 8);

    const int bh = blockIdx.x * 2 + sub;
    const int b = bh / 6, h = bh - b * 6;
    const int w = b & 63;

    // async q/k/v loads: 49 rows x 32 halves = 64 bytes = FOUR 16B chunks/row
    {
        const char* qg = (const char*)(g_q + (size_t)bh * 1568);
        const char* kg = (const char*)(g_k + (size_t)bh * 1568);
        const char* vg = (const char*)(g_v + (size_t)bh * 1568);
        for (int i = tt; i < 196; i += 128) {
            int r = i >> 2, c = i & 3;
            cp16(&sQ[sub][r][c * 8], qg + r * 64 + c * 16);
            cp16(&sK[sub][r][c * 8], kg + r * 64 + c * 16);
            cp16(&sV[sub][r][c * 8], vg + r * 64 + c * 16);
        }
        cp_commit();
        // zero V pad rows 49..63 (only V pad matters: P[j>=49] == 0, avoid NaN)
        for (int i = tt; i < 15 * 20; i += 128) {
            int r = 49 + i / 20, c = i - (i / 20) * 20;
            ((u32*)&sV[sub][r][0])[c] = 0u;
        }
        asm volatile("cp.async.wait_all;\n" ::: "memory");
    }
    __syncthreads();

    // Q fragments (16 rows per warp, k = 0..31)
    u32 qa[2][4];
    ldsm4(qa[0], &sQ[sub][warp * 16 + lrow][lcol]);
    ldsm4(qa[1], &sQ[sub][warp * 16 + lrow][16 + lcol]);

    // S = Q K^T : warp owns 16 rows x 64 cols
    float s[8][4] = {};
#pragma unroll
    for (int g = 0; g < 4; ++g) {
        u32 kb[2][4];
        ldsm4(kb[0], &sK[sub][g * 16 + brow][bcol]);        // k 0..15
        ldsm4(kb[1], &sK[sub][g * 16 + brow][16 + bcol]);   // k 16..31
        mma16816(s[2 * g],     qa[0], &kb[0][0]);
        mma16816(s[2 * g],     qa[1], &kb[1][0]);
        mma16816(s[2 * g + 1], qa[0], &kb[0][2]);
        mma16816(s[2 * g + 1], qa[1], &kb[1][2]);
    }

    // logits = s*scale + mask, masked softmax (rows r0, r1)
    const int r0 = warp * 16 + lr, r1 = r0 + 8;
    const float* m0p = mask + (size_t)w * 2401 + min(r0, 48) * 49;
    const float* m1p = mask + (size_t)w * 2401 + min(r1, 48) * 49;
#pragma unroll
    for (int nt = 0; nt < 8; ++nt) {
        int j0 = nt * 8 + lw * 2, j1 = j0 + 1;
        s[nt][0] = (j0 < 49) ? s[nt][0] * ATT_SCALE + m0p[j0] : -1e30f;
        s[nt][1] = (j1 < 49) ? s[nt][1] * ATT_SCALE + m0p[j1] : -1e30f;
        s[nt][2] = (j0 < 49) ? s[nt][2] * ATT_SCALE + m1p[j0] : -1e30f;
        s[nt][3] = (j1 < 49) ? s[nt][3] * ATT_SCALE + m1p[j1] : -1e30f;
    }
    float mx0 = -1e30f, mx1 = -1e30f;
#pragma unroll
    for (int nt = 0; nt < 8; ++nt) {
        mx0 = fmaxf(mx0, fmaxf(s[nt][0], s[nt][1]));
        mx1 = fmaxf(mx1, fmaxf(s[nt][2], s[nt][3]));
    }
    mx0 = fmaxf(mx0, __shfl_xor_sync(0xffffffffu, mx0, 1));
    mx0 = fmaxf(mx0, __shfl_xor_sync(0xffffffffu, mx0, 2));
    mx1 = fmaxf(mx1, __shfl_xor_sync(0xffffffffu, mx1, 1));
    mx1 = fmaxf(mx1, __shfl_xor_sync(0xffffffffu, mx1, 2));
    float sm0 = 0.f, sm1 = 0.f;
#pragma unroll
    for (int nt = 0; nt < 8; ++nt) {
        s[nt][0] = __expf(s[nt][0] - mx0);
        s[nt][1] = __expf(s[nt][1] - mx0);
        s[nt][2] = __expf(s[nt][2] - mx1);
        s[nt][3] = __expf(s[nt][3] - mx1);
        sm0 += s[nt][0] + s[nt][1];
        sm1 += s[nt][2] + s[nt][3];
    }
    sm0 += __shfl_xor_sync(0xffffffffu, sm0, 1);
    sm0 += __shfl_xor_sync(0xffffffffu, sm0, 2);
    sm1 += __shfl_xor_sync(0xffffffffu, sm1, 1);
    sm1 += __shfl_xor_sync(0xffffffffu, sm1, 2);
    const float inv0 = 1.f / sm0, inv1 = 1.f / sm1;

    // P (fp16 A-fragments), then O = P V  (V B-frags via ldmatrix.trans)
    u32 pa[4][4];
#pragma unroll
    for (int kk = 0; kk < 4; ++kk) {
        pa[kk][0] = pack2(s[2 * kk][0] * inv0, s[2 * kk][1] * inv0);
        pa[kk][1] = pack2(s[2 * kk][2] * inv1, s[2 * kk][3] * inv1);
        pa[kk][2] = pack2(s[2 * kk + 1][0] * inv0, s[2 * kk + 1][1] * inv0);
        pa[kk][3] = pack2(s[2 * kk + 1][2] * inv1, s[2 * kk + 1][3] * inv1);
    }
    float o[4][4] = {};
#pragma unroll
    for (int kk = 0; kk < 4; ++kk) {
        u32 vb[2][4];
        ldsm4t(vb[0], &sV[sub][kk * 16 + lrow][lcol]);        // d 0..15
        ldsm4t(vb[1], &sV[sub][kk * 16 + lrow][16 + lcol]);   // d 16..31
        mma16816(o[0], pa[kk], &vb[0][0]);
        mma16816(o[1], pa[kk], &vb[0][2]);
        mma16816(o[2], pa[kk], &vb[1][0]);
        mma16816(o[3], pa[kk], &vb[1][2]);
    }

    // store O as [b*49+n][h*32+d] fp16 for proj GEMM
#pragma unroll
    for (int dt = 0; dt < 4; ++dt) {
        int dd = dt * 8 + lw * 2;
        if (r0 < 49)
            *(__half2*)(g_o + ((size_t)(b * 49 + r0) * 6 + h) * 32 + dd) =
                __floats2half2_rn(o[dt][0], o[dt][1]);
        if (r1 < 49)
            *(__half2*)(g_o + ((size_t)(b * 49 + r1) * 6 + h) * 32 + dd) =
                __floats2half2_rn(o[dt][2], o[dt][3]);
    }
}

// ---------------- launch ----------------------------------------------------
extern "C" void kernel_launch(void* const* d_in, const int* in_sizes, int n_in,
                              void* d_out, int out_size) {
    const float* x      = (const float*)d_in[0];
    const float* mask   = (const float*)d_in[1];
    const float* qkv_w  = (const float*)d_in[2];
    const float* qkv_b  = (const float*)d_in[3];
    const float* proj_w = (const float*)d_in[4];
    const float* proj_b = (const float*)d_in[5];
    float* out = (float*)d_out;

    cudaFuncSetAttribute(gemm_qkv_kernel,
                         cudaFuncAttributeMaxDynamicSharedMemorySize, GSMEM_BYTES);
    cudaFuncSetAttribute(gemm_proj_kernel,
                         cudaFuncAttributeMaxDynamicSharedMemorySize, GSMEM_BYTES);

    prep_kernel<<<(576 * 192 + 255) / 256, 256>>>(qkv_w, proj_w);
    gemm_qkv_kernel<<<MROW / 128, 256, GSMEM_BYTES>>>(x, qkv_b);
    attn_kernel<<<BB * HH / 2, 256>>>(mask);
    gemm_proj_kernel<<<MROW / 128, 256, GSMEM_BYTES>>>(proj_b, out);
}